// round 5
// baseline (speedup 1.0000x reference)
#include <cuda_runtime.h>
#include <cuda_bf16.h>
#include <math.h>

#define N_NODES 100000
#define N_EDGES 1600000
#define N_TOT   1700000   // edges + self loops
#define N_GRAPHS 256
#define BN_EPS 1e-5f

#define SCAN_BLOCKS 512
#define SCAN_CHUNK  ((N_NODES + SCAN_BLOCKS - 1) / SCAN_BLOCKS)   // 196

// ---------------- scratch (device globals; no runtime allocation) -------------
__device__ int   g_idx64;               // 1 if indices are int64, 0 if int32
__device__ int   g_deg[N_NODES];
__device__ float g_dinv[N_NODES];
__device__ int   g_off[N_NODES + 1];
__device__ int   g_blocksum[SCAN_BLOCKS];
__device__ int   g_cursor[N_NODES];
__device__ int   g_srcarr[N_TOT];
__device__ float g_normarr[N_TOT];
__device__ float g_hA[(size_t)N_NODES * 200];  // aggregated (BN'd) input to GEMM (padded stride)
__device__ float g_hB[(size_t)N_NODES * 200];  // layer output (padded stride)
__device__ float g_stats[512];                 // [0..255]=sum, [256..511]=sumsq
__device__ float g_scale[256];
__device__ float g_shift[256];
__device__ int   g_gstart[N_GRAPHS + 1];

// dual-width index loader
__device__ __forceinline__ int idx_at(const void* p, long i, int is64) {
    if (is64) return (int)((const long long*)p)[i];
    return ((const int*)p)[i];
}

// ---------------- dtype detection ----------------
__global__ void __launch_bounds__(32) k_detect(const int* __restrict__ ei32) {
    if (threadIdx.x != 0) return;
    int any = 0;
    for (int k = 0; k < 64; k++) {
        if (ei32[2 * k + 1] != 0) { any = 1; break; }
    }
    g_idx64 = !any;
}

// ---------------- graph prep ----------------
__global__ void __launch_bounds__(256) k_deg_init() {
    int n = blockIdx.x * blockDim.x + threadIdx.x;
    if (n < N_NODES) g_deg[n] = 1;  // self loop
}

__global__ void __launch_bounds__(256) k_deg_edges(const void* __restrict__ ei) {
    int e = blockIdx.x * blockDim.x + threadIdx.x;
    if (e < N_EDGES) {
        int is64 = g_idx64;
        int d = idx_at(ei, (long)N_EDGES + e, is64);
        if ((unsigned)d < N_NODES) atomicAdd(&g_deg[d], 1);
    }
}

__global__ void __launch_bounds__(256) k_dinv() {
    int n = blockIdx.x * blockDim.x + threadIdx.x;
    if (n < N_NODES) g_dinv[n] = rsqrtf((float)g_deg[n]);
}

__global__ void __launch_bounds__(256) k_scan1() {
    __shared__ int sh[256];
    int b = blockIdx.x;
    int t = threadIdx.x;
    const int PER_T = (SCAN_CHUNK + 255) / 256;  // 1
    int base = b * SCAN_CHUNK;
    int s = 0;
    int vals[PER_T];
    #pragma unroll
    for (int i = 0; i < PER_T; i++) {
        int idx = base + t * PER_T + i;
        int v = (idx < N_NODES && t * PER_T + i < SCAN_CHUNK) ? g_deg[idx] : 0;
        vals[i] = v;
        s += v;
    }
    sh[t] = s;
    __syncthreads();
    for (int o = 1; o < 256; o <<= 1) {
        int v = (t >= o) ? sh[t - o] : 0;
        __syncthreads();
        sh[t] += v;
        __syncthreads();
    }
    int pre = (t == 0) ? 0 : sh[t - 1];
    #pragma unroll
    for (int i = 0; i < PER_T; i++) {
        int idx = base + t * PER_T + i;
        if (idx < N_NODES && t * PER_T + i < SCAN_CHUNK) {
            g_off[idx] = pre;
            pre += vals[i];
        }
    }
    if (t == 255) g_blocksum[b] = sh[255];
}

__global__ void __launch_bounds__(256) k_scan2() {
    __shared__ int sh[256];
    int t = threadIdx.x;
    int a0 = g_blocksum[2 * t];
    int a1 = g_blocksum[2 * t + 1];
    sh[t] = a0 + a1;
    __syncthreads();
    for (int o = 1; o < 256; o <<= 1) {
        int v = (t >= o) ? sh[t - o] : 0;
        __syncthreads();
        sh[t] += v;
        __syncthreads();
    }
    int pre = (t == 0) ? 0 : sh[t - 1];
    g_blocksum[2 * t] = pre;
    g_blocksum[2 * t + 1] = pre + a0;
    if (t == 255) g_off[N_NODES] = sh[255];
}

__global__ void __launch_bounds__(256) k_scan3() {
    int n = blockIdx.x * blockDim.x + threadIdx.x;
    if (n < N_NODES) g_off[n] += g_blocksum[n / SCAN_CHUNK];
}

__global__ void __launch_bounds__(256) k_selfloop() {
    int n = blockIdx.x * blockDim.x + threadIdx.x;
    if (n < N_NODES) {
        int o = g_off[n];
        g_srcarr[o] = n;
        float di = g_dinv[n];
        g_normarr[o] = di * di;
        g_cursor[n] = o + 1;
    }
}

__global__ void __launch_bounds__(256) k_fill(const void* __restrict__ ei) {
    int e = blockIdx.x * blockDim.x + threadIdx.x;
    if (e < N_EDGES) {
        int is64 = g_idx64;
        int s = idx_at(ei, e, is64);
        int d = idx_at(ei, (long)N_EDGES + e, is64);
        if ((unsigned)s < N_NODES && (unsigned)d < N_NODES) {
            int pos = atomicAdd(&g_cursor[d], 1);
            if ((unsigned)pos < N_TOT) {
                g_srcarr[pos] = s;
                g_normarr[pos] = g_dinv[s] * g_dinv[d];
            }
        }
    }
}

// ---------------- batchnorm stats ----------------
__global__ void __launch_bounds__(512) k_zero_stats() {
    int i = threadIdx.x;
    if (i < 512) g_stats[i] = 0.0f;
}

// grid (ceil(FI/32), 64), block (32, 8). STRIDE = row stride of the input.
__global__ void __launch_bounds__(256) k_stats(const float* __restrict__ xp, int FI,
                                               int STRIDE, int useParam) {
    const float* x = useParam ? xp : g_hB;
    int f = blockIdx.x * 32 + threadIdx.x;
    float s = 0.f, sq = 0.f;
    if (f < FI) {
        for (int n = blockIdx.y * blockDim.y + threadIdx.y; n < N_NODES;
             n += gridDim.y * blockDim.y) {
            float v = x[(size_t)n * STRIDE + f];
            s += v;
            sq += v * v;
        }
    }
    __shared__ float shs[8][32];
    __shared__ float shq[8][32];
    shs[threadIdx.y][threadIdx.x] = s;
    shq[threadIdx.y][threadIdx.x] = sq;
    __syncthreads();
    if (threadIdx.y == 0 && f < FI) {
        float ts = 0.f, tq = 0.f;
        #pragma unroll
        for (int y = 0; y < 8; y++) { ts += shs[y][threadIdx.x]; tq += shq[y][threadIdx.x]; }
        atomicAdd(&g_stats[f], ts);
        atomicAdd(&g_stats[256 + f], tq);
    }
}

// writes zeros for k >= FI so padded columns are exactly zeroed in the gather
__global__ void __launch_bounds__(256) k_finalize(const float* __restrict__ gam,
                                                  const float* __restrict__ bet, int FI) {
    int k = threadIdx.x;
    if (k < FI) {
        float m = g_stats[k] * (1.0f / N_NODES);
        float v = g_stats[256 + k] * (1.0f / N_NODES) - m * m;
        float a = gam[k] * rsqrtf(v + BN_EPS);
        g_scale[k] = a;
        g_shift[k] = bet[k] - m * a;
    } else if (k < 256) {
        g_scale[k] = 0.f;
        g_shift[k] = 0.f;
    }
}

// ---------------- layer-1 gather (scalar, external x, FI=7 -> padded 8) ------
__global__ void __launch_bounds__(256) k_gather1(const float* __restrict__ x) {
    const int FI = 7, FIP = 8, LPN = 8;
    int gid = blockIdx.x * blockDim.x + threadIdx.x;
    int node = gid / LPN;
    int lane = gid % LPN;
    if (node >= N_NODES) return;
    int beg = g_off[node], end = g_off[node + 1];
    float acc = 0.f, sumw = 0.f;
    for (int e = beg; e < end; e++) {
        int s = __ldg(&g_srcarr[e]);
        float wn = __ldg(&g_normarr[e]);
        sumw += wn;
        if (lane < FI) acc += wn * __ldg(&x[(size_t)s * FI + lane]);
    }
    g_hA[(size_t)node * FIP + lane] = g_scale[lane] * acc + g_shift[lane] * sumw;
}

// ---------------- vectorized gather (float4 rows, padded strides) ------------
// LPN = FIP/4 lanes per node; each lane owns one float4 chunk.
template <int LPN>
__global__ void __launch_bounds__(256) k_gatherv() {
    int gid = blockIdx.x * blockDim.x + threadIdx.x;
    int node = gid / LPN;
    int lane = gid - node * LPN;
    if (node >= N_NODES) return;
    int beg = g_off[node], end = g_off[node + 1];
    const float4* in4 = (const float4*)g_hB;
    float4* out4 = (float4*)g_hA;
    float ax = 0.f, ay = 0.f, az = 0.f, aw = 0.f, sumw = 0.f;
    for (int e = beg; e < end; e++) {
        int s = __ldg(&g_srcarr[e]);
        float wn = __ldg(&g_normarr[e]);
        sumw += wn;
        float4 v = __ldg(&in4[(size_t)s * LPN + lane]);
        ax += wn * v.x; ay += wn * v.y; az += wn * v.z; aw += wn * v.w;
    }
    int c = lane * 4;
    float4 r;
    r.x = g_scale[c + 0] * ax + g_shift[c + 0] * sumw;
    r.y = g_scale[c + 1] * ay + g_shift[c + 1] * sumw;
    r.z = g_scale[c + 2] * az + g_shift[c + 2] * sumw;
    r.w = g_scale[c + 3] * aw + g_shift[c + 3] * sumw;
    out4[(size_t)node * LPN + lane] = r;
}

// ---------------- GEMM: hB = relu(hA @ W + bias), padded strides -------------
// grid (ceil(N/64), ceil(FO/64)), block 256
template <int FI, int FIP, int FO, int FOP>
__global__ void __launch_bounds__(256) k_gemm(const float* __restrict__ W,
                                              const float* __restrict__ bias) {
    const int KC = 32;
    __shared__ float xs[64][KC + 1];
    __shared__ float ws[KC][64];
    const float* in = g_hA;
    float* out = g_hB;

    int tid = threadIdx.x;
    int tx = tid & 15, ty = tid >> 4;
    int n0 = blockIdx.x * 64, j0 = blockIdx.y * 64;

    float acc[4][4];
    #pragma unroll
    for (int r = 0; r < 4; r++)
        #pragma unroll
        for (int c = 0; c < 4; c++) acc[r][c] = 0.f;

    for (int kc = 0; kc < FI; kc += KC) {
        for (int i = tid; i < 64 * KC; i += 256) {
            int nn = i / KC, kk = i % KC;
            int k = kc + kk, n = n0 + nn;
            float v = 0.f;
            if (k < FI && n < N_NODES) v = in[(size_t)n * FIP + k];
            xs[nn][kk] = v;
        }
        for (int i = tid; i < KC * 64; i += 256) {
            int kk = i / 64, c = i % 64;
            int k = kc + kk, j = j0 + c;
            float v = 0.f;
            if (k < FI && j < FO) v = W[k * FO + j];
            ws[kk][c] = v;
        }
        __syncthreads();
        int kmax = (FI - kc < KC) ? (FI - kc) : KC;
        for (int kk = 0; kk < kmax; kk++) {
            float4 wv = *(const float4*)&ws[kk][tx * 4];
            float xv[4];
            #pragma unroll
            for (int r = 0; r < 4; r++) xv[r] = xs[ty * 4 + r][kk];
            #pragma unroll
            for (int r = 0; r < 4; r++) {
                acc[r][0] += xv[r] * wv.x;
                acc[r][1] += xv[r] * wv.y;
                acc[r][2] += xv[r] * wv.z;
                acc[r][3] += xv[r] * wv.w;
            }
        }
        __syncthreads();
    }
    #pragma unroll
    for (int r = 0; r < 4; r++) {
        int n = n0 + ty * 4 + r;
        if (n >= N_NODES) continue;
        #pragma unroll
        for (int c = 0; c < 4; c++) {
            int j = j0 + tx * 4 + c;
            if (j < FO) {
                float v = acc[r][c] + __ldg(&bias[j]);
                out[(size_t)n * FOP + j] = v > 0.f ? v : 0.f;
            }
        }
    }
}

// ---------------- pooling boundaries (batch is sorted) ----------------
__global__ void __launch_bounds__(256) k_gstart(const void* __restrict__ batch) {
    int g = blockIdx.x * blockDim.x + threadIdx.x;
    if (g > N_GRAPHS) return;
    if (g == N_GRAPHS) { g_gstart[g] = N_NODES; return; }
    int is64 = g_idx64;
    int lo = 0, hi = N_NODES;
    while (lo < hi) {
        int mid = (lo + hi) >> 1;
        if (idx_at(batch, mid, is64) < g) lo = mid + 1; else hi = mid;
    }
    g_gstart[g] = lo;
}

// ---------------- fused mean-pool + MLP head (hB stride 200) ----------------
__global__ void __launch_bounds__(256) k_poolmlp(const float* __restrict__ Wl1,
                                                 const float* __restrict__ bl1,
                                                 const float* __restrict__ Wl2,
                                                 const float* __restrict__ bl2,
                                                 float* __restrict__ out) {
    const int FO = 199, FOP = 200;
    __shared__ float pooled[FO];
    __shared__ float t1[49];
    int g = blockIdx.x;
    int s = g_gstart[g], e = g_gstart[g + 1];
    int f = threadIdx.x;
    if (f < FO) {
        float acc = 0.f;
        for (int n = s; n < e; n++) acc += g_hB[(size_t)n * FOP + f];
        int cnt = e - s;
        pooled[f] = acc / (float)(cnt > 0 ? cnt : 1);
    }
    __syncthreads();
    if (f < 49) {
        float a = bl1[f];
        for (int k = 0; k < FO; k++) a += pooled[k] * Wl1[k * 49 + f];
        t1[f] = a;
    }
    __syncthreads();
    if (f < 2) {
        float a = bl2[f];
        for (int k = 0; k < 49; k++) a += t1[k] * Wl2[k * 2 + f];
        out[g * 2 + f] = a;
    }
}

// ---------------- launch ----------------
extern "C" void kernel_launch(void* const* d_in, const int* in_sizes, int n_in,
                              void* d_out, int out_size) {
    const float* x     = (const float*)d_in[0];
    const void*  ei    = d_in[1];
    const void*  batch = d_in[2];
    const float* bn0g = (const float*)d_in[3];
    const float* bn0b = (const float*)d_in[4];
    const float* bn1g = (const float*)d_in[5];
    const float* bn1b = (const float*)d_in[6];
    const float* bn2g = (const float*)d_in[7];
    const float* bn2b = (const float*)d_in[8];
    const float* W1  = (const float*)d_in[9];
    const float* b1  = (const float*)d_in[10];
    const float* W2  = (const float*)d_in[11];
    const float* b2  = (const float*)d_in[12];
    const float* W3  = (const float*)d_in[13];
    const float* b3  = (const float*)d_in[14];
    const float* Wl1 = (const float*)d_in[15];
    const float* bl1 = (const float*)d_in[16];
    const float* Wl2 = (const float*)d_in[17];
    const float* bl2 = (const float*)d_in[18];
    float* out = (float*)d_out;

    const int NB_N = (N_NODES + 255) / 256;
    const int NB_E = (N_EDGES + 255) / 256;

    // dtype detection + graph preprocessing
    k_detect<<<1, 32>>>((const int*)ei);
    k_deg_init<<<NB_N, 256>>>();
    k_deg_edges<<<NB_E, 256>>>(ei);
    k_dinv<<<NB_N, 256>>>();
    k_scan1<<<SCAN_BLOCKS, 256>>>();
    k_scan2<<<1, 256>>>();
    k_scan3<<<NB_N, 256>>>();
    k_selfloop<<<NB_N, 256>>>();
    k_fill<<<NB_E, 256>>>(ei);
    k_gstart<<<2, 256>>>(batch);

    dim3 sblk(32, 8);
    const int NB_G8  = ((N_NODES * 8)  + 255) / 256;
    const int NB_G18 = ((N_NODES * 18) + 255) / 256;
    const int NB_G34 = ((N_NODES * 34) + 255) / 256;

    // ---- layer 1: stats(x) -> gather(BN(x)) -> gemm W1 (+b1, relu)
    k_zero_stats<<<1, 512>>>();
    k_stats<<<dim3(1, 64), sblk>>>(x, 7, 7, 1);
    k_finalize<<<1, 256>>>(bn0g, bn0b, 7);
    k_gather1<<<NB_G8, 256>>>(x);
    k_gemm<7, 8, 71, 72><<<dim3((N_NODES + 63) / 64, 2), 256>>>(W1, b1);

    // ---- layer 2
    k_zero_stats<<<1, 512>>>();
    k_stats<<<dim3(3, 64), sblk>>>(nullptr, 71, 72, 0);
    k_finalize<<<1, 256>>>(bn1g, bn1b, 71);
    k_gatherv<18><<<NB_G18, 256>>>();
    k_gemm<71, 72, 135, 136><<<dim3((N_NODES + 63) / 64, 3), 256>>>(W2, b2);

    // ---- layer 3
    k_zero_stats<<<1, 512>>>();
    k_stats<<<dim3(5, 64), sblk>>>(nullptr, 135, 136, 0);
    k_finalize<<<1, 256>>>(bn2g, bn2b, 135);
    k_gatherv<34><<<NB_G34, 256>>>();
    k_gemm<135, 136, 199, 200><<<dim3((N_NODES + 63) / 64, 4), 256>>>(W3, b3);

    // ---- pool + head
    k_poolmlp<<<N_GRAPHS, 256>>>(Wl1, bl1, Wl2, bl2, out);
}

// round 6
// speedup vs baseline: 1.1191x; 1.1191x over previous
#include <cuda_runtime.h>
#include <cuda_bf16.h>
#include <math.h>

#define N_NODES 100000
#define N_EDGES 1600000
#define N_TOT   1700000   // edges + self loops
#define N_GRAPHS 256
#define BN_EPS 1e-5f

#define SCAN_BLOCKS 512
#define SCAN_CHUNK  ((N_NODES + SCAN_BLOCKS - 1) / SCAN_BLOCKS)   // 196

// ---------------- scratch (device globals; no runtime allocation) -------------
__device__ int   g_idx64;               // 1 if indices are int64, 0 if int32
__device__ int   g_deg[N_NODES];
__device__ float g_dinv[N_NODES];
__device__ int   g_off[N_NODES + 1];
__device__ int   g_blocksum[SCAN_BLOCKS];
__device__ int   g_cursor[N_NODES];
__device__ int   g_srcarr[N_TOT];
__device__ float g_normarr[N_TOT];
__device__ float g_hA[(size_t)N_NODES * 200 + 1024];  // aggregated (BN'd) input (padded)
__device__ float g_hB[(size_t)N_NODES * 200 + 1024];  // layer output (padded)
__device__ float g_stats[512];                 // [0..255]=sum, [256..511]=sumsq
__device__ float g_scale[256];
__device__ float g_shift[256];
__device__ int   g_gstart[N_GRAPHS + 1];

// dual-width index loader
__device__ __forceinline__ int idx_at(const void* p, long i, int is64) {
    if (is64) return (int)((const long long*)p)[i];
    return ((const int*)p)[i];
}

// ---------------- dtype detection ----------------
__global__ void __launch_bounds__(32) k_detect(const int* __restrict__ ei32) {
    if (threadIdx.x != 0) return;
    int any = 0;
    for (int k = 0; k < 64; k++) {
        if (ei32[2 * k + 1] != 0) { any = 1; break; }
    }
    g_idx64 = !any;
}

// ---------------- graph prep ----------------
__global__ void __launch_bounds__(256) k_deg_init() {
    int n = blockIdx.x * blockDim.x + threadIdx.x;
    if (n < N_NODES) g_deg[n] = 1;  // self loop
}

__global__ void __launch_bounds__(256) k_deg_edges(const void* __restrict__ ei) {
    int e = blockIdx.x * blockDim.x + threadIdx.x;
    if (e < N_EDGES) {
        int is64 = g_idx64;
        int d = idx_at(ei, (long)N_EDGES + e, is64);
        if ((unsigned)d < N_NODES) atomicAdd(&g_deg[d], 1);
    }
}

__global__ void __launch_bounds__(256) k_dinv() {
    int n = blockIdx.x * blockDim.x + threadIdx.x;
    if (n < N_NODES) g_dinv[n] = rsqrtf((float)g_deg[n]);
}

__global__ void __launch_bounds__(256) k_scan1() {
    __shared__ int sh[256];
    int b = blockIdx.x;
    int t = threadIdx.x;
    const int PER_T = (SCAN_CHUNK + 255) / 256;  // 1
    int base = b * SCAN_CHUNK;
    int s = 0;
    int vals[PER_T];
    #pragma unroll
    for (int i = 0; i < PER_T; i++) {
        int idx = base + t * PER_T + i;
        int v = (idx < N_NODES && t * PER_T + i < SCAN_CHUNK) ? g_deg[idx] : 0;
        vals[i] = v;
        s += v;
    }
    sh[t] = s;
    __syncthreads();
    for (int o = 1; o < 256; o <<= 1) {
        int v = (t >= o) ? sh[t - o] : 0;
        __syncthreads();
        sh[t] += v;
        __syncthreads();
    }
    int pre = (t == 0) ? 0 : sh[t - 1];
    #pragma unroll
    for (int i = 0; i < PER_T; i++) {
        int idx = base + t * PER_T + i;
        if (idx < N_NODES && t * PER_T + i < SCAN_CHUNK) {
            g_off[idx] = pre;
            pre += vals[i];
        }
    }
    if (t == 255) g_blocksum[b] = sh[255];
}

__global__ void __launch_bounds__(256) k_scan2() {
    __shared__ int sh[256];
    int t = threadIdx.x;
    int a0 = g_blocksum[2 * t];
    int a1 = g_blocksum[2 * t + 1];
    sh[t] = a0 + a1;
    __syncthreads();
    for (int o = 1; o < 256; o <<= 1) {
        int v = (t >= o) ? sh[t - o] : 0;
        __syncthreads();
        sh[t] += v;
        __syncthreads();
    }
    int pre = (t == 0) ? 0 : sh[t - 1];
    g_blocksum[2 * t] = pre;
    g_blocksum[2 * t + 1] = pre + a0;
    if (t == 255) g_off[N_NODES] = sh[255];
}

__global__ void __launch_bounds__(256) k_scan3() {
    int n = blockIdx.x * blockDim.x + threadIdx.x;
    if (n < N_NODES) g_off[n] += g_blocksum[n / SCAN_CHUNK];
}

__global__ void __launch_bounds__(256) k_selfloop() {
    int n = blockIdx.x * blockDim.x + threadIdx.x;
    if (n < N_NODES) {
        int o = g_off[n];
        g_srcarr[o] = n;
        float di = g_dinv[n];
        g_normarr[o] = di * di;
        g_cursor[n] = o + 1;
    }
}

__global__ void __launch_bounds__(256) k_fill(const void* __restrict__ ei) {
    int e = blockIdx.x * blockDim.x + threadIdx.x;
    if (e < N_EDGES) {
        int is64 = g_idx64;
        int s = idx_at(ei, e, is64);
        int d = idx_at(ei, (long)N_EDGES + e, is64);
        if ((unsigned)s < N_NODES && (unsigned)d < N_NODES) {
            int pos = atomicAdd(&g_cursor[d], 1);
            if ((unsigned)pos < N_TOT) {
                g_srcarr[pos] = s;
                g_normarr[pos] = g_dinv[s] * g_dinv[d];
            }
        }
    }
}

// ---------------- batchnorm stats ----------------
__global__ void __launch_bounds__(512) k_zero_stats() {
    int i = threadIdx.x;
    if (i < 512) g_stats[i] = 0.0f;
}

// grid (ceil(FI/32), 64), block (32, 8). STRIDE = row stride of the input.
__global__ void __launch_bounds__(256) k_stats(const float* __restrict__ xp, int FI,
                                               int STRIDE, int useParam) {
    const float* x = useParam ? xp : g_hB;
    int f = blockIdx.x * 32 + threadIdx.x;
    float s = 0.f, sq = 0.f;
    if (f < FI) {
        for (int n = blockIdx.y * blockDim.y + threadIdx.y; n < N_NODES;
             n += gridDim.y * blockDim.y) {
            float v = x[(size_t)n * STRIDE + f];
            s += v;
            sq += v * v;
        }
    }
    __shared__ float shs[8][32];
    __shared__ float shq[8][32];
    shs[threadIdx.y][threadIdx.x] = s;
    shq[threadIdx.y][threadIdx.x] = sq;
    __syncthreads();
    if (threadIdx.y == 0 && f < FI) {
        float ts = 0.f, tq = 0.f;
        #pragma unroll
        for (int y = 0; y < 8; y++) { ts += shs[y][threadIdx.x]; tq += shq[y][threadIdx.x]; }
        atomicAdd(&g_stats[f], ts);
        atomicAdd(&g_stats[256 + f], tq);
    }
}

// writes zeros for k >= FI so padded columns are exactly zeroed in the gather
__global__ void __launch_bounds__(256) k_finalize(const float* __restrict__ gam,
                                                  const float* __restrict__ bet, int FI) {
    int k = threadIdx.x;
    if (k < FI) {
        float m = g_stats[k] * (1.0f / N_NODES);
        float v = g_stats[256 + k] * (1.0f / N_NODES) - m * m;
        float a = gam[k] * rsqrtf(v + BN_EPS);
        g_scale[k] = a;
        g_shift[k] = bet[k] - m * a;
    } else if (k < 256) {
        g_scale[k] = 0.f;
        g_shift[k] = 0.f;
    }
}

// ---------------- layer-1 gather (scalar, external x, FI=7 -> padded 8) ------
__global__ void __launch_bounds__(256) k_gather1(const float* __restrict__ x) {
    const int FI = 7, FIP = 8, LPN = 8;
    int gid = blockIdx.x * blockDim.x + threadIdx.x;
    int node = gid / LPN;
    int lane = gid % LPN;
    if (node >= N_NODES) return;
    int beg = g_off[node], end = g_off[node + 1];
    float acc = 0.f, sumw = 0.f;
    for (int e = beg; e < end; e++) {
        int s = __ldg(&g_srcarr[e]);
        float wn = __ldg(&g_normarr[e]);
        sumw += wn;
        if (lane < FI) acc += wn * __ldg(&x[(size_t)s * FI + lane]);
    }
    g_hA[(size_t)node * FIP + lane] = g_scale[lane] * acc + g_shift[lane] * sumw;
}

// ---------------- vectorized gather (float4 rows, padded strides) ------------
// LPN = FIP/4 lanes per node; each lane owns one float4 chunk.
template <int LPN>
__global__ void __launch_bounds__(256) k_gatherv() {
    int gid = blockIdx.x * blockDim.x + threadIdx.x;
    int node = gid / LPN;
    int lane = gid - node * LPN;
    if (node >= N_NODES) return;
    int beg = g_off[node], end = g_off[node + 1];
    const float4* in4 = (const float4*)g_hB;
    float4* out4 = (float4*)g_hA;
    float ax = 0.f, ay = 0.f, az = 0.f, aw = 0.f, sumw = 0.f;
    for (int e = beg; e < end; e++) {
        int s = __ldg(&g_srcarr[e]);
        float wn = __ldg(&g_normarr[e]);
        sumw += wn;
        float4 v = __ldg(&in4[(size_t)s * LPN + lane]);
        ax += wn * v.x; ay += wn * v.y; az += wn * v.z; aw += wn * v.w;
    }
    int c = lane * 4;
    float4 r;
    r.x = g_scale[c + 0] * ax + g_shift[c + 0] * sumw;
    r.y = g_scale[c + 1] * ay + g_shift[c + 1] * sumw;
    r.z = g_scale[c + 2] * az + g_shift[c + 2] * sumw;
    r.w = g_scale[c + 3] * aw + g_shift[c + 3] * sumw;
    out4[(size_t)node * LPN + lane] = r;
}

// ---------------- GEMM v2: hB = relu(hA @ W + bias) --------------------------
// 128x64 tile, 256 threads, 8x4 register tile, KC=16.
// k-tail: only ws is guarded (w=0 kills stale xs contributions).
template <int FI, int FIP, int FO, int FOP>
__global__ void __launch_bounds__(256) k_gemm2(const float* __restrict__ W,
                                               const float* __restrict__ bias) {
    const int KC = 16;
    const int NROW = 128;
    __shared__ float xs[KC][NROW + 4];   // 132 floats/row: float4-aligned, no LDS conflicts
    __shared__ float ws[KC][64];

    int tid = threadIdx.x;
    int tx = tid & 15;    // j quad
    int ty = tid >> 4;    // row octet
    int n0 = blockIdx.x * NROW, j0 = blockIdx.y * 64;

    const float4* in4 = (const float4*)g_hA;
    const int FIP4 = FIP / 4;
    float* out = g_hB;

    float acc[8][4];
    #pragma unroll
    for (int r = 0; r < 8; r++)
        #pragma unroll
        for (int c = 0; c < 4; c++) acc[r][c] = 0.f;

    const int KCH = (FI + KC - 1) / KC;
    for (int ch = 0; ch < KCH; ch++) {
        int kc = ch * KC;
        // stage ws: 16x64 = 1024 elems, 4 per thread (guarded; zero for k>=FI / j>=FO)
        #pragma unroll
        for (int i = 0; i < 4; i++) {
            int idx = tid + i * 256;
            int kk = idx >> 6, c = idx & 63;
            int k = kc + kk, j = j0 + c;
            ws[kk][c] = (k < FI && j < FO) ? __ldg(&W[k * FO + j]) : 0.f;
        }
        // stage xs transposed: 128 rows x 4 float4 chunks = 512, 2 per thread (no guards)
        #pragma unroll
        for (int i = 0; i < 2; i++) {
            int cch = tid + i * 256;
            int nn = cch & 127, q = cch >> 7;
            float4 v = in4[(size_t)(n0 + nn) * FIP4 + (kc >> 2) + q];
            xs[q * 4 + 0][nn] = v.x;
            xs[q * 4 + 1][nn] = v.y;
            xs[q * 4 + 2][nn] = v.z;
            xs[q * 4 + 3][nn] = v.w;
        }
        __syncthreads();
        #pragma unroll
        for (int kk = 0; kk < KC; kk++) {
            float4 wv = *(const float4*)&ws[kk][tx * 4];
            const float4* xr = (const float4*)&xs[kk][ty * 8];
            float4 x0 = xr[0];
            float4 x1 = xr[1];
            float xv[8] = {x0.x, x0.y, x0.z, x0.w, x1.x, x1.y, x1.z, x1.w};
            #pragma unroll
            for (int r = 0; r < 8; r++) {
                acc[r][0] += xv[r] * wv.x;
                acc[r][1] += xv[r] * wv.y;
                acc[r][2] += xv[r] * wv.z;
                acc[r][3] += xv[r] * wv.w;
            }
        }
        __syncthreads();
    }

    // epilogue: bias + relu, guarded stores
    #pragma unroll
    for (int r = 0; r < 8; r++) {
        int n = n0 + ty * 8 + r;
        if (n >= N_NODES) continue;
        #pragma unroll
        for (int c = 0; c < 4; c++) {
            int j = j0 + tx * 4 + c;
            if (j < FO) {
                float v = acc[r][c] + __ldg(&bias[j]);
                out[(size_t)n * FOP + j] = v > 0.f ? v : 0.f;
            }
        }
    }
}

// ---------------- pooling boundaries (batch is sorted) ----------------
__global__ void __launch_bounds__(256) k_gstart(const void* __restrict__ batch) {
    int g = blockIdx.x * blockDim.x + threadIdx.x;
    if (g > N_GRAPHS) return;
    if (g == N_GRAPHS) { g_gstart[g] = N_NODES; return; }
    int is64 = g_idx64;
    int lo = 0, hi = N_NODES;
    while (lo < hi) {
        int mid = (lo + hi) >> 1;
        if (idx_at(batch, mid, is64) < g) lo = mid + 1; else hi = mid;
    }
    g_gstart[g] = lo;
}

// ---------------- fused mean-pool + MLP head (hB stride 200) ----------------
__global__ void __launch_bounds__(256) k_poolmlp(const float* __restrict__ Wl1,
                                                 const float* __restrict__ bl1,
                                                 const float* __restrict__ Wl2,
                                                 const float* __restrict__ bl2,
                                                 float* __restrict__ out) {
    const int FO = 199, FOP = 200;
    __shared__ float pooled[FO];
    __shared__ float t1[49];
    int g = blockIdx.x;
    int s = g_gstart[g], e = g_gstart[g + 1];
    int f = threadIdx.x;
    if (f < FO) {
        float acc = 0.f;
        for (int n = s; n < e; n++) acc += g_hB[(size_t)n * FOP + f];
        int cnt = e - s;
        pooled[f] = acc / (float)(cnt > 0 ? cnt : 1);
    }
    __syncthreads();
    if (f < 49) {
        float a = bl1[f];
        for (int k = 0; k < FO; k++) a += pooled[k] * Wl1[k * 49 + f];
        t1[f] = a;
    }
    __syncthreads();
    if (f < 2) {
        float a = bl2[f];
        for (int k = 0; k < 49; k++) a += t1[k] * Wl2[k * 2 + f];
        out[g * 2 + f] = a;
    }
}

// ---------------- launch ----------------
extern "C" void kernel_launch(void* const* d_in, const int* in_sizes, int n_in,
                              void* d_out, int out_size) {
    const float* x     = (const float*)d_in[0];
    const void*  ei    = d_in[1];
    const void*  batch = d_in[2];
    const float* bn0g = (const float*)d_in[3];
    const float* bn0b = (const float*)d_in[4];
    const float* bn1g = (const float*)d_in[5];
    const float* bn1b = (const float*)d_in[6];
    const float* bn2g = (const float*)d_in[7];
    const float* bn2b = (const float*)d_in[8];
    const float* W1  = (const float*)d_in[9];
    const float* b1  = (const float*)d_in[10];
    const float* W2  = (const float*)d_in[11];
    const float* b2  = (const float*)d_in[12];
    const float* W3  = (const float*)d_in[13];
    const float* b3  = (const float*)d_in[14];
    const float* Wl1 = (const float*)d_in[15];
    const float* bl1 = (const float*)d_in[16];
    const float* Wl2 = (const float*)d_in[17];
    const float* bl2 = (const float*)d_in[18];
    float* out = (float*)d_out;

    const int NB_N = (N_NODES + 255) / 256;
    const int NB_E = (N_EDGES + 255) / 256;

    // dtype detection + graph preprocessing
    k_detect<<<1, 32>>>((const int*)ei);
    k_deg_init<<<NB_N, 256>>>();
    k_deg_edges<<<NB_E, 256>>>(ei);
    k_dinv<<<NB_N, 256>>>();
    k_scan1<<<SCAN_BLOCKS, 256>>>();
    k_scan2<<<1, 256>>>();
    k_scan3<<<NB_N, 256>>>();
    k_selfloop<<<NB_N, 256>>>();
    k_fill<<<NB_E, 256>>>(ei);
    k_gstart<<<2, 256>>>(batch);

    dim3 sblk(32, 8);
    const int NB_G8  = ((N_NODES * 8)  + 255) / 256;
    const int NB_G18 = ((N_NODES * 18) + 255) / 256;
    const int NB_G34 = ((N_NODES * 34) + 255) / 256;
    const int GX = (N_NODES + 127) / 128;

    // ---- layer 1: stats(x) -> gather(BN(x)) -> gemm W1 (+b1, relu)
    k_zero_stats<<<1, 512>>>();
    k_stats<<<dim3(1, 64), sblk>>>(x, 7, 7, 1);
    k_finalize<<<1, 256>>>(bn0g, bn0b, 7);
    k_gather1<<<NB_G8, 256>>>(x);
    k_gemm2<7, 8, 71, 72><<<dim3(GX, 2), 256>>>(W1, b1);

    // ---- layer 2
    k_zero_stats<<<1, 512>>>();
    k_stats<<<dim3(3, 64), sblk>>>(nullptr, 71, 72, 0);
    k_finalize<<<1, 256>>>(bn1g, bn1b, 71);
    k_gatherv<18><<<NB_G18, 256>>>();
    k_gemm2<71, 72, 135, 136><<<dim3(GX, 3), 256>>>(W2, b2);

    // ---- layer 3
    k_zero_stats<<<1, 512>>>();
    k_stats<<<dim3(5, 64), sblk>>>(nullptr, 135, 136, 0);
    k_finalize<<<1, 256>>>(bn2g, bn2b, 135);
    k_gatherv<34><<<NB_G34, 256>>>();
    k_gemm2<135, 136, 199, 200><<<dim3(GX, 4), 256>>>(W3, b3);

    // ---- pool + head
    k_poolmlp<<<N_GRAPHS, 256>>>(Wl1, bl1, Wl2, bl2, out);
}

// round 7
// speedup vs baseline: 1.2195x; 1.0897x over previous
#include <cuda_runtime.h>
#include <cuda_bf16.h>
#include <math.h>

#define N_NODES 100000
#define N_PAD   100096   // N_NODES rounded up to 128 (full GEMM tiles)
#define N_EDGES 1600000
#define N_TOT   1700000  // edges + self loops
#define N_GRAPHS 256
#define BN_EPS 1e-5f

#define SCAN_BLOCKS 512
#define SCAN_CHUNK  ((N_NODES + SCAN_BLOCKS - 1) / SCAN_BLOCKS)   // 196

// ---------------- scratch (device globals; no runtime allocation) -------------
__device__ int   g_idx64;               // 1 if indices are int64, 0 if int32
__device__ int   g_deg[N_NODES];
__device__ float g_dinv[N_NODES];
__device__ int   g_off[N_NODES + 1];
__device__ int   g_blocksum[SCAN_BLOCKS];
__device__ int   g_cursor[N_NODES];
__device__ int   g_srcarr[N_TOT];
__device__ float g_normarr[N_TOT];
__device__ float g_hA[(size_t)N_PAD * 200];   // aggregated (BN'd) input (padded)
__device__ float g_hB[(size_t)N_PAD * 200];   // layer output (padded)
__device__ float g_stats[512];                // [0..255]=sum, [256..511]=sumsq
__device__ float g_scale[256];
__device__ float g_shift[256];
__device__ int   g_gstart[N_GRAPHS + 1];

// dual-width index loader
__device__ __forceinline__ int idx_at(const void* p, long i, int is64) {
    if (is64) return (int)((const long long*)p)[i];
    return ((const int*)p)[i];
}

// ---------------- init: deg=1, stats=0, dtype detect ----------------
__global__ void __launch_bounds__(256) k_init(const int* __restrict__ ei32) {
    int n = blockIdx.x * blockDim.x + threadIdx.x;
    if (n < N_NODES) g_deg[n] = 1;  // self loop
    if (n < 512) g_stats[n] = 0.0f;
    if (n == 0) {
        // int64 little-endian values < 2^31: all odd 32-bit words are 0.
        int any = 0;
        for (int k = 0; k < 64; k++) {
            if (ei32[2 * k + 1] != 0) { any = 1; break; }
        }
        g_idx64 = !any;
    }
}

__global__ void __launch_bounds__(256) k_deg_edges(const void* __restrict__ ei) {
    int e = blockIdx.x * blockDim.x + threadIdx.x;
    if (e < N_EDGES) {
        int is64 = g_idx64;
        int d = idx_at(ei, (long)N_EDGES + e, is64);
        if ((unsigned)d < N_NODES) atomicAdd(&g_deg[d], 1);
    }
}

// pass 1: per-block scan + dinv
__global__ void __launch_bounds__(256) k_scan1() {
    __shared__ int sh[256];
    int b = blockIdx.x;
    int t = threadIdx.x;
    int idx = b * SCAN_CHUNK + t;
    int v = 0;
    if (t < SCAN_CHUNK && idx < N_NODES) {
        v = g_deg[idx];
        g_dinv[idx] = rsqrtf((float)v);
    }
    sh[t] = v;
    __syncthreads();
    for (int o = 1; o < 256; o <<= 1) {
        int a = (t >= o) ? sh[t - o] : 0;
        __syncthreads();
        sh[t] += a;
        __syncthreads();
    }
    if (t < SCAN_CHUNK && idx < N_NODES) g_off[idx] = sh[t] - v;  // exclusive
    if (t == 255) g_blocksum[b] = sh[255];
}

// pass 2: scan block sums + graph-boundary binary search
__global__ void __launch_bounds__(256) k_scan2(const void* __restrict__ batch) {
    __shared__ int sh[256];
    int t = threadIdx.x;
    int a0 = g_blocksum[2 * t];
    int a1 = g_blocksum[2 * t + 1];
    sh[t] = a0 + a1;
    __syncthreads();
    for (int o = 1; o < 256; o <<= 1) {
        int v = (t >= o) ? sh[t - o] : 0;
        __syncthreads();
        sh[t] += v;
        __syncthreads();
    }
    int pre = (t == 0) ? 0 : sh[t - 1];
    g_blocksum[2 * t] = pre;
    g_blocksum[2 * t + 1] = pre + a0;
    if (t == 255) g_off[N_NODES] = sh[255];
    // graph start boundaries (batch is sorted); g == t
    int is64 = g_idx64;
    int lo = 0, hi = N_NODES;
    while (lo < hi) {
        int mid = (lo + hi) >> 1;
        if (idx_at(batch, mid, is64) < t) lo = mid + 1; else hi = mid;
    }
    g_gstart[t] = lo;
    if (t == 0) g_gstart[N_GRAPHS] = N_NODES;
}

// pass 3: add block offsets + write self-loop entry + init cursor
__global__ void __launch_bounds__(256) k_scan3() {
    int n = blockIdx.x * blockDim.x + threadIdx.x;
    if (n < N_NODES) {
        int o = g_off[n] + g_blocksum[n / SCAN_CHUNK];
        g_off[n] = o;
        g_srcarr[o] = n;
        float di = g_dinv[n];
        g_normarr[o] = di * di;
        g_cursor[n] = o + 1;
    }
}

__global__ void __launch_bounds__(256) k_fill(const void* __restrict__ ei) {
    int e = blockIdx.x * blockDim.x + threadIdx.x;
    if (e < N_EDGES) {
        int is64 = g_idx64;
        int s = idx_at(ei, e, is64);
        int d = idx_at(ei, (long)N_EDGES + e, is64);
        if ((unsigned)s < N_NODES && (unsigned)d < N_NODES) {
            int pos = atomicAdd(&g_cursor[d], 1);
            if ((unsigned)pos < N_TOT) {
                g_srcarr[pos] = s;
                g_normarr[pos] = g_dinv[s] * g_dinv[d];
            }
        }
    }
}

// ---------------- stats over external x (layer 0 only) ----------------
// grid (1, 64), block (32, 8)
__global__ void __launch_bounds__(256) k_stats_x(const float* __restrict__ x, int FI) {
    int f = threadIdx.x;
    float s = 0.f, sq = 0.f;
    if (f < FI) {
        for (int n = blockIdx.y * blockDim.y + threadIdx.y; n < N_NODES;
             n += gridDim.y * blockDim.y) {
            float v = x[(size_t)n * FI + f];
            s += v;
            sq += v * v;
        }
    }
    __shared__ float shs[8][32];
    __shared__ float shq[8][32];
    shs[threadIdx.y][threadIdx.x] = s;
    shq[threadIdx.y][threadIdx.x] = sq;
    __syncthreads();
    if (threadIdx.y == 0 && f < FI) {
        float ts = 0.f, tq = 0.f;
        #pragma unroll
        for (int y = 0; y < 8; y++) { ts += shs[y][threadIdx.x]; tq += shq[y][threadIdx.x]; }
        atomicAdd(&g_stats[f], ts);
        atomicAdd(&g_stats[256 + f], tq);
    }
}

// reads stats -> scale/shift, zeroes padded entries, then re-zeroes stats
__global__ void __launch_bounds__(256) k_finalize(const float* __restrict__ gam,
                                                  const float* __restrict__ bet, int FI) {
    int k = threadIdx.x;
    if (k < FI) {
        float m = g_stats[k] * (1.0f / N_NODES);
        float v = g_stats[256 + k] * (1.0f / N_NODES) - m * m;
        float a = gam[k] * rsqrtf(v + BN_EPS);
        g_scale[k] = a;
        g_shift[k] = bet[k] - m * a;
    } else {
        g_scale[k] = 0.f;
        g_shift[k] = 0.f;
    }
    g_stats[k] = 0.f;
    g_stats[256 + k] = 0.f;
}

// ---------------- layer-1 gather (scalar, external x, FI=7 -> padded 8) ------
__global__ void __launch_bounds__(256) k_gather1(const float* __restrict__ x) {
    const int FI = 7, FIP = 8, LPN = 8;
    int gid = blockIdx.x * blockDim.x + threadIdx.x;
    int node = gid / LPN;
    int lane = gid % LPN;
    if (node >= N_NODES) return;
    int beg = g_off[node], end = g_off[node + 1];
    float acc = 0.f, sumw = 0.f;
    for (int e = beg; e < end; e++) {
        int s = __ldg(&g_srcarr[e]);
        float wn = __ldg(&g_normarr[e]);
        sumw += wn;
        if (lane < FI) acc += wn * __ldg(&x[(size_t)s * FI + lane]);
    }
    g_hA[(size_t)node * FIP + lane] = g_scale[lane] * acc + g_shift[lane] * sumw;
}

// ---------------- vectorized gather (float4 rows, padded strides) ------------
template <int LPN>
__global__ void __launch_bounds__(256) k_gatherv() {
    int gid = blockIdx.x * blockDim.x + threadIdx.x;
    int node = gid / LPN;
    int lane = gid - node * LPN;
    if (node >= N_NODES) return;
    int beg = g_off[node], end = g_off[node + 1];
    const float4* in4 = (const float4*)g_hB;
    float4* out4 = (float4*)g_hA;
    float ax = 0.f, ay = 0.f, az = 0.f, aw = 0.f, sumw = 0.f;
    for (int e = beg; e < end; e++) {
        int s = __ldg(&g_srcarr[e]);
        float wn = __ldg(&g_normarr[e]);
        sumw += wn;
        float4 v = __ldg(&in4[(size_t)s * LPN + lane]);
        ax += wn * v.x; ay += wn * v.y; az += wn * v.z; aw += wn * v.w;
    }
    int c = lane * 4;
    float4 r;
    r.x = g_scale[c + 0] * ax + g_shift[c + 0] * sumw;
    r.y = g_scale[c + 1] * ay + g_shift[c + 1] * sumw;
    r.z = g_scale[c + 2] * az + g_shift[c + 2] * sumw;
    r.w = g_scale[c + 3] * aw + g_shift[c + 3] * sumw;
    out4[(size_t)node * LPN + lane] = r;
}

// ---------------- GEMM v2 + fused BN stats -----------------------------------
// 128x64 tile, 256 threads, 8x4 register tile, KC=16.
// If STATS: accumulates column sum/sumsq of the (relu'd) output into g_stats.
template <int FI, int FIP, int FO, int FOP, bool STATS>
__global__ void __launch_bounds__(256) k_gemm2(const float* __restrict__ W,
                                               const float* __restrict__ bias) {
    const int KC = 16;
    const int NROW = 128;
    __shared__ float xs[KC][NROW + 4];   // 2112 floats; reused for stats reduction
    __shared__ float ws[KC][64];

    int tid = threadIdx.x;
    int tx = tid & 15;    // j quad
    int ty = tid >> 4;    // row octet
    int n0 = blockIdx.x * NROW, j0 = blockIdx.y * 64;

    const float4* in4 = (const float4*)g_hA;
    const int FIP4 = FIP / 4;
    float* out = g_hB;

    float acc[8][4];
    #pragma unroll
    for (int r = 0; r < 8; r++)
        #pragma unroll
        for (int c = 0; c < 4; c++) acc[r][c] = 0.f;

    const int KCH = (FI + KC - 1) / KC;
    for (int ch = 0; ch < KCH; ch++) {
        int kc = ch * KC;
        #pragma unroll
        for (int i = 0; i < 4; i++) {
            int idx = tid + i * 256;
            int kk = idx >> 6, c = idx & 63;
            int k = kc + kk, j = j0 + c;
            ws[kk][c] = (k < FI && j < FO) ? __ldg(&W[k * FO + j]) : 0.f;
        }
        #pragma unroll
        for (int i = 0; i < 2; i++) {
            int cch = tid + i * 256;
            int nn = cch & 127, q = cch >> 7;
            float4 v = in4[(size_t)(n0 + nn) * FIP4 + (kc >> 2) + q];
            xs[q * 4 + 0][nn] = v.x;
            xs[q * 4 + 1][nn] = v.y;
            xs[q * 4 + 2][nn] = v.z;
            xs[q * 4 + 3][nn] = v.w;
        }
        __syncthreads();
        #pragma unroll
        for (int kk = 0; kk < KC; kk++) {
            float4 wv = *(const float4*)&ws[kk][tx * 4];
            const float4* xr = (const float4*)&xs[kk][ty * 8];
            float4 x0 = xr[0];
            float4 x1 = xr[1];
            float xv[8] = {x0.x, x0.y, x0.z, x0.w, x1.x, x1.y, x1.z, x1.w};
            #pragma unroll
            for (int r = 0; r < 8; r++) {
                acc[r][0] += xv[r] * wv.x;
                acc[r][1] += xv[r] * wv.y;
                acc[r][2] += xv[r] * wv.z;
                acc[r][3] += xv[r] * wv.w;
            }
        }
        __syncthreads();
    }

    // epilogue: bias + relu, guarded stores; optional stats accumulation
    float csum[4] = {0.f, 0.f, 0.f, 0.f};
    float csq[4]  = {0.f, 0.f, 0.f, 0.f};
    #pragma unroll
    for (int r = 0; r < 8; r++) {
        int n = n0 + ty * 8 + r;
        if (n >= N_NODES) continue;
        #pragma unroll
        for (int c = 0; c < 4; c++) {
            int j = j0 + tx * 4 + c;
            if (j < FO) {
                float v = acc[r][c] + __ldg(&bias[j]);
                v = v > 0.f ? v : 0.f;
                out[(size_t)n * FOP + j] = v;
                if (STATS) { csum[c] += v; csq[c] += v * v; }
            }
        }
    }
    if (STATS) {
        // reuse xs as reduction buffer: [16][64] sums + [16][64] squares
        float* red = &xs[0][0];
        #pragma unroll
        for (int c = 0; c < 4; c++) {
            red[ty * 64 + tx * 4 + c] = csum[c];
            red[1024 + ty * 64 + tx * 4 + c] = csq[c];
        }
        __syncthreads();
        if (tid < 64) {
            float s = 0.f, q = 0.f;
            #pragma unroll
            for (int y = 0; y < 16; y++) {
                s += red[y * 64 + tid];
                q += red[1024 + y * 64 + tid];
            }
            int j = j0 + tid;
            if (j < FO) {
                atomicAdd(&g_stats[j], s);
                atomicAdd(&g_stats[256 + j], q);
            }
        }
    }
}

// ---------------- fused mean-pool + MLP head (hB stride 200) ----------------
__global__ void __launch_bounds__(256) k_poolmlp(const float* __restrict__ Wl1,
                                                 const float* __restrict__ bl1,
                                                 const float* __restrict__ Wl2,
                                                 const float* __restrict__ bl2,
                                                 float* __restrict__ out) {
    const int FO = 199, FOP = 200;
    __shared__ float pooled[FO];
    __shared__ float t1[49];
    int g = blockIdx.x;
    int s = g_gstart[g], e = g_gstart[g + 1];
    int f = threadIdx.x;
    if (f < FO) {
        float acc = 0.f;
        for (int n = s; n < e; n++) acc += g_hB[(size_t)n * FOP + f];
        int cnt = e - s;
        pooled[f] = acc / (float)(cnt > 0 ? cnt : 1);
    }
    __syncthreads();
    if (f < 49) {
        float a = bl1[f];
        for (int k = 0; k < FO; k++) a += pooled[k] * Wl1[k * 49 + f];
        t1[f] = a;
    }
    __syncthreads();
    if (f < 2) {
        float a = bl2[f];
        for (int k = 0; k < 49; k++) a += t1[k] * Wl2[k * 2 + f];
        out[g * 2 + f] = a;
    }
}

// ---------------- launch ----------------
extern "C" void kernel_launch(void* const* d_in, const int* in_sizes, int n_in,
                              void* d_out, int out_size) {
    const float* x     = (const float*)d_in[0];
    const void*  ei    = d_in[1];
    const void*  batch = d_in[2];
    const float* bn0g = (const float*)d_in[3];
    const float* bn0b = (const float*)d_in[4];
    const float* bn1g = (const float*)d_in[5];
    const float* bn1b = (const float*)d_in[6];
    const float* bn2g = (const float*)d_in[7];
    const float* bn2b = (const float*)d_in[8];
    const float* W1  = (const float*)d_in[9];
    const float* b1  = (const float*)d_in[10];
    const float* W2  = (const float*)d_in[11];
    const float* b2  = (const float*)d_in[12];
    const float* W3  = (const float*)d_in[13];
    const float* b3  = (const float*)d_in[14];
    const float* Wl1 = (const float*)d_in[15];
    const float* bl1 = (const float*)d_in[16];
    const float* Wl2 = (const float*)d_in[17];
    const float* bl2 = (const float*)d_in[18];
    float* out = (float*)d_out;

    const int NB_N = (N_NODES + 255) / 256;
    const int NB_E = (N_EDGES + 255) / 256;

    // graph preprocessing (merged)
    k_init<<<NB_N, 256>>>((const int*)ei);
    k_deg_edges<<<NB_E, 256>>>(ei);
    k_scan1<<<SCAN_BLOCKS, 256>>>();
    k_scan2<<<1, 256>>>(batch);
    k_scan3<<<NB_N, 256>>>();
    k_fill<<<NB_E, 256>>>(ei);

    dim3 sblk(32, 8);
    const int NB_G8  = ((N_NODES * 8)  + 255) / 256;
    const int NB_G18 = ((N_NODES * 18) + 255) / 256;
    const int NB_G34 = ((N_NODES * 34) + 255) / 256;
    const int GX = N_PAD / 128;

    // ---- layer 1
    k_stats_x<<<dim3(1, 64), sblk>>>(x, 7);
    k_finalize<<<1, 256>>>(bn0g, bn0b, 7);
    k_gather1<<<NB_G8, 256>>>(x);
    k_gemm2<7, 8, 71, 72, true><<<dim3(GX, 2), 256>>>(W1, b1);

    // ---- layer 2
    k_finalize<<<1, 256>>>(bn1g, bn1b, 71);
    k_gatherv<18><<<NB_G18, 256>>>();
    k_gemm2<71, 72, 135, 136, true><<<dim3(GX, 3), 256>>>(W2, b2);

    // ---- layer 3
    k_finalize<<<1, 256>>>(bn2g, bn2b, 135);
    k_gatherv<34><<<NB_G34, 256>>>();
    k_gemm2<135, 136, 199, 200, false><<<dim3(GX, 4), 256>>>(W3, b3);

    // ---- pool + head
    k_poolmlp<<<N_GRAPHS, 256>>>(Wl1, bl1, Wl2, bl2, out);
}

// round 9
// speedup vs baseline: 1.2254x; 1.0049x over previous
#include <cuda_runtime.h>
#include <cuda_bf16.h>
#include <math.h>
#include <stdint.h>

#define N_NODES 100000
#define N_PAD   100096   // N_NODES rounded up to 128 (full GEMM tiles)
#define N_EDGES 1600000
#define N_TOT   1700000  // edges + self loops
#define N_GRAPHS 256
#define BN_EPS 1e-5f

#define SCAN_BLOCKS 512
#define SCAN_CHUNK  ((N_NODES + SCAN_BLOCKS - 1) / SCAN_BLOCKS)   // 196

// ---------------- scratch (device globals; no runtime allocation) -------------
__device__ int   g_idx64;
__device__ int   g_deg[N_NODES];
__device__ float g_dinv[N_NODES];
__device__ int   g_off[N_NODES + 1];
__device__ int   g_blocksum[SCAN_BLOCKS];
__device__ int   g_cursor[N_NODES];
__device__ int   g_srcarr[N_TOT];
__device__ float g_normarr[N_TOT];
__device__ float g_hA[(size_t)N_PAD * 200];   // aggregated (BN'd) input (padded); pad rows stay 0
__device__ float g_hB[(size_t)N_PAD * 200];   // layer output (padded)
__device__ float g_stats[512];
__device__ float g_scale[256];
__device__ float g_shift[256];
__device__ int   g_gstart[N_GRAPHS + 1];

__device__ __forceinline__ uint32_t f2tf32(float f) {
    uint32_t r;
    asm("cvt.rna.tf32.f32 %0, %1;" : "=r"(r) : "f"(f));
    return r;
}

// dual-width index loader
__device__ __forceinline__ int idx_at(const void* p, long i, int is64) {
    if (is64) return (int)((const long long*)p)[i];
    return ((const int*)p)[i];
}

// ---------------- init ----------------
__global__ void __launch_bounds__(256) k_init(const int* __restrict__ ei32) {
    int n = blockIdx.x * blockDim.x + threadIdx.x;
    if (n < N_NODES) g_deg[n] = 1;
    if (n < 512) g_stats[n] = 0.0f;
    if (n == 0) {
        int any = 0;
        for (int k = 0; k < 64; k++)
            if (ei32[2 * k + 1] != 0) { any = 1; break; }
        g_idx64 = !any;
    }
}

__global__ void __launch_bounds__(256) k_deg_edges(const void* __restrict__ ei) {
    int e = blockIdx.x * blockDim.x + threadIdx.x;
    if (e < N_EDGES) {
        int is64 = g_idx64;
        int d = idx_at(ei, (long)N_EDGES + e, is64);
        if ((unsigned)d < N_NODES) atomicAdd(&g_deg[d], 1);
    }
}

__global__ void __launch_bounds__(256) k_scan1() {
    __shared__ int sh[256];
    int b = blockIdx.x, t = threadIdx.x;
    int idx = b * SCAN_CHUNK + t;
    int v = 0;
    if (t < SCAN_CHUNK && idx < N_NODES) {
        v = g_deg[idx];
        g_dinv[idx] = rsqrtf((float)v);
    }
    sh[t] = v;
    __syncthreads();
    for (int o = 1; o < 256; o <<= 1) {
        int a = (t >= o) ? sh[t - o] : 0;
        __syncthreads();
        sh[t] += a;
        __syncthreads();
    }
    if (t < SCAN_CHUNK && idx < N_NODES) g_off[idx] = sh[t] - v;
    if (t == 255) g_blocksum[b] = sh[255];
}

__global__ void __launch_bounds__(256) k_scan2(const void* __restrict__ batch) {
    __shared__ int sh[256];
    int t = threadIdx.x;
    int a0 = g_blocksum[2 * t];
    int a1 = g_blocksum[2 * t + 1];
    sh[t] = a0 + a1;
    __syncthreads();
    for (int o = 1; o < 256; o <<= 1) {
        int v = (t >= o) ? sh[t - o] : 0;
        __syncthreads();
        sh[t] += v;
        __syncthreads();
    }
    int pre = (t == 0) ? 0 : sh[t - 1];
    g_blocksum[2 * t] = pre;
    g_blocksum[2 * t + 1] = pre + a0;
    if (t == 255) g_off[N_NODES] = sh[255];
    int is64 = g_idx64;
    int lo = 0, hi = N_NODES;
    while (lo < hi) {
        int mid = (lo + hi) >> 1;
        if (idx_at(batch, mid, is64) < t) lo = mid + 1; else hi = mid;
    }
    g_gstart[t] = lo;
    if (t == 0) g_gstart[N_GRAPHS] = N_NODES;
}

__global__ void __launch_bounds__(256) k_scan3() {
    int n = blockIdx.x * blockDim.x + threadIdx.x;
    if (n < N_NODES) {
        int o = g_off[n] + g_blocksum[n / SCAN_CHUNK];
        g_off[n] = o;
        g_srcarr[o] = n;
        float di = g_dinv[n];
        g_normarr[o] = di * di;
        g_cursor[n] = o + 1;
    }
}

__global__ void __launch_bounds__(256) k_fill(const void* __restrict__ ei) {
    int e = blockIdx.x * blockDim.x + threadIdx.x;
    if (e < N_EDGES) {
        int is64 = g_idx64;
        int s = idx_at(ei, e, is64);
        int d = idx_at(ei, (long)N_EDGES + e, is64);
        if ((unsigned)s < N_NODES && (unsigned)d < N_NODES) {
            int pos = atomicAdd(&g_cursor[d], 1);
            if ((unsigned)pos < N_TOT) {
                g_srcarr[pos] = s;
                g_normarr[pos] = g_dinv[s] * g_dinv[d];
            }
        }
    }
}

// ---------------- stats over external x (layer 0 only) ----------------
__global__ void __launch_bounds__(256) k_stats_x(const float* __restrict__ x, int FI) {
    int f = threadIdx.x;
    float s = 0.f, sq = 0.f;
    if (f < FI) {
        for (int n = blockIdx.y * blockDim.y + threadIdx.y; n < N_NODES;
             n += gridDim.y * blockDim.y) {
            float v = x[(size_t)n * FI + f];
            s += v;
            sq += v * v;
        }
    }
    __shared__ float shs[8][32];
    __shared__ float shq[8][32];
    shs[threadIdx.y][threadIdx.x] = s;
    shq[threadIdx.y][threadIdx.x] = sq;
    __syncthreads();
    if (threadIdx.y == 0 && f < FI) {
        float ts = 0.f, tq = 0.f;
        #pragma unroll
        for (int y = 0; y < 8; y++) { ts += shs[y][threadIdx.x]; tq += shq[y][threadIdx.x]; }
        atomicAdd(&g_stats[f], ts);
        atomicAdd(&g_stats[256 + f], tq);
    }
}

__global__ void __launch_bounds__(256) k_finalize(const float* __restrict__ gam,
                                                  const float* __restrict__ bet, int FI) {
    int k = threadIdx.x;
    if (k < FI) {
        float m = g_stats[k] * (1.0f / N_NODES);
        float v = g_stats[256 + k] * (1.0f / N_NODES) - m * m;
        float a = gam[k] * rsqrtf(v + BN_EPS);
        g_scale[k] = a;
        g_shift[k] = bet[k] - m * a;
    } else {
        g_scale[k] = 0.f;
        g_shift[k] = 0.f;
    }
    g_stats[k] = 0.f;
    g_stats[256 + k] = 0.f;
}

// ---------------- layer-1 gather (scalar, external x, FI=7 -> padded 8) ------
__global__ void __launch_bounds__(256) k_gather1(const float* __restrict__ x) {
    const int FI = 7, FIP = 8, LPN = 8;
    int gid = blockIdx.x * blockDim.x + threadIdx.x;
    int node = gid / LPN;
    int lane = gid % LPN;
    if (node >= N_NODES) return;
    int beg = g_off[node], end = g_off[node + 1];
    float acc = 0.f, sumw = 0.f;
    for (int e = beg; e < end; e++) {
        int s = __ldg(&g_srcarr[e]);
        float wn = __ldg(&g_normarr[e]);
        sumw += wn;
        if (lane < FI) acc += wn * __ldg(&x[(size_t)s * FI + lane]);
    }
    g_hA[(size_t)node * FIP + lane] = g_scale[lane] * acc + g_shift[lane] * sumw;
}

// ---------------- vectorized gather (float4 rows, padded strides) ------------
template <int LPN>
__global__ void __launch_bounds__(256) k_gatherv() {
    int gid = blockIdx.x * blockDim.x + threadIdx.x;
    int node = gid / LPN;
    int lane = gid - node * LPN;
    if (node >= N_NODES) return;
    int beg = g_off[node], end = g_off[node + 1];
    const float4* in4 = (const float4*)g_hB;
    float4* out4 = (float4*)g_hA;
    float ax = 0.f, ay = 0.f, az = 0.f, aw = 0.f, sumw = 0.f;
    for (int e = beg; e < end; e++) {
        int s = __ldg(&g_srcarr[e]);
        float wn = __ldg(&g_normarr[e]);
        sumw += wn;
        float4 v = __ldg(&in4[(size_t)s * LPN + lane]);
        ax += wn * v.x; ay += wn * v.y; az += wn * v.z; aw += wn * v.w;
    }
    int c = lane * 4;
    float4 r;
    r.x = g_scale[c + 0] * ax + g_shift[c + 0] * sumw;
    r.y = g_scale[c + 1] * ay + g_shift[c + 1] * sumw;
    r.z = g_scale[c + 2] * az + g_shift[c + 2] * sumw;
    r.w = g_scale[c + 3] * aw + g_shift[c + 3] * sumw;
    out4[(size_t)node * LPN + lane] = r;
}

// ---------------- tf32 mma.sync GEMM: hB = relu(hA @ W + bias) ---------------
// CTA tile 128x64, 256 threads = 8 warps (4 M x 2 N). Warp tile 32x32 via
// m16n8k8 tf32 mma (2 m-tiles x 4 n-tiles). KC=16 per stage.
template <int FI, int FIP, int FO, int FOP, bool STATS>
__global__ void __launch_bounds__(256) k_gemm_mma(const float* __restrict__ W,
                                                  const float* __restrict__ bias) {
    const int KC = 16;
    __shared__ uint32_t As[KC][132];   // k-major, padded
    __shared__ uint32_t Ws[KC][68];
    __shared__ float sred[64];
    __shared__ float sqred[64];

    int tid = threadIdx.x;
    int wid = tid >> 5, lane = tid & 31;
    int grp = lane >> 2, tg = lane & 3;
    int mwarp = (wid & 3) * 32;   // warp M offset in tile
    int nwarp = (wid >> 2) * 32;  // warp N offset in tile
    int n0 = blockIdx.x * 128, j0 = blockIdx.y * 64;

    if (STATS && tid < 64) { sred[tid] = 0.f; sqred[tid] = 0.f; }

    float c[2][4][4];
    #pragma unroll
    for (int mi = 0; mi < 2; mi++)
        #pragma unroll
        for (int ni = 0; ni < 4; ni++)
            #pragma unroll
            for (int q = 0; q < 4; q++) c[mi][ni][q] = 0.f;

    const int KCH = (FIP + KC - 1) / KC;
    int am = tid & 127;          // row for A staging
    int ahalf = tid >> 7;        // k half (0/1)
    for (int ch = 0; ch < KCH; ch++) {
        int kc = ch * KC;
        // stage A (128 x 16) transposed to k-major, tf32
        {
            const float* arow = g_hA + (size_t)(n0 + am) * FIP;
            #pragma unroll
            for (int q = 0; q < 2; q++) {
                int k = kc + ahalf * 8 + q * 4;
                float4 v = make_float4(0.f, 0.f, 0.f, 0.f);
                if (k < FIP) v = *(const float4*)(arow + k);
                int kk = ahalf * 8 + q * 4;
                As[kk + 0][am] = f2tf32(v.x);
                As[kk + 1][am] = f2tf32(v.y);
                As[kk + 2][am] = f2tf32(v.z);
                As[kk + 3][am] = f2tf32(v.w);
            }
        }
        // stage W (16 x 64), zero-guarded
        #pragma unroll
        for (int i = 0; i < 4; i++) {
            int idx = tid + i * 256;
            int kk = idx >> 6, nn = idx & 63;
            int k = kc + kk, j = j0 + nn;
            float v = (k < FI && j < FO) ? __ldg(&W[k * FO + j]) : 0.f;
            Ws[kk][nn] = f2tf32(v);
        }
        __syncthreads();
        #pragma unroll
        for (int ks = 0; ks < 2; ks++) {
            int kb = ks * 8;
            uint32_t a[2][4];
            #pragma unroll
            for (int mi = 0; mi < 2; mi++) {
                int m = mwarp + mi * 16 + grp;
                a[mi][0] = As[kb + tg][m];
                a[mi][1] = As[kb + tg][m + 8];
                a[mi][2] = As[kb + 4 + tg][m];
                a[mi][3] = As[kb + 4 + tg][m + 8];
            }
            uint32_t b[4][2];
            #pragma unroll
            for (int ni = 0; ni < 4; ni++) {
                int nn = nwarp + ni * 8 + grp;
                b[ni][0] = Ws[kb + tg][nn];
                b[ni][1] = Ws[kb + 4 + tg][nn];
            }
            #pragma unroll
            for (int mi = 0; mi < 2; mi++)
                #pragma unroll
                for (int ni = 0; ni < 4; ni++) {
                    asm volatile(
                        "mma.sync.aligned.m16n8k8.row.col.f32.tf32.tf32.f32 "
                        "{%0,%1,%2,%3}, {%4,%5,%6,%7}, {%8,%9}, {%0,%1,%2,%3};"
                        : "+f"(c[mi][ni][0]), "+f"(c[mi][ni][1]),
                          "+f"(c[mi][ni][2]), "+f"(c[mi][ni][3])
                        : "r"(a[mi][0]), "r"(a[mi][1]), "r"(a[mi][2]), "r"(a[mi][3]),
                          "r"(b[ni][0]), "r"(b[ni][1]));
                }
        }
        __syncthreads();
    }

    // epilogue: bias + relu, store, optional stats
    float lsum[8], lsq[8];
    #pragma unroll
    for (int q = 0; q < 8; q++) { lsum[q] = 0.f; lsq[q] = 0.f; }
    #pragma unroll
    for (int mi = 0; mi < 2; mi++) {
        int r0 = n0 + mwarp + mi * 16 + grp;
        int r1 = r0 + 8;
        #pragma unroll
        for (int ni = 0; ni < 4; ni++) {
            int jb = j0 + nwarp + ni * 8 + 2 * tg;
            float bj0 = (jb < FO) ? __ldg(&bias[jb]) : 0.f;
            float bj1 = (jb + 1 < FO) ? __ldg(&bias[jb + 1]) : 0.f;
            float v00 = c[mi][ni][0] + bj0; v00 = v00 > 0.f ? v00 : 0.f;
            float v01 = c[mi][ni][1] + bj1; v01 = v01 > 0.f ? v01 : 0.f;
            float v10 = c[mi][ni][2] + bj0; v10 = v10 > 0.f ? v10 : 0.f;
            float v11 = c[mi][ni][3] + bj1; v11 = v11 > 0.f ? v11 : 0.f;
            bool ok0 = (r0 < N_NODES), ok1 = (r1 < N_NODES);
            if (ok0 && jb < FO)     g_hB[(size_t)r0 * FOP + jb]     = v00;
            if (ok0 && jb + 1 < FO) g_hB[(size_t)r0 * FOP + jb + 1] = v01;
            if (ok1 && jb < FO)     g_hB[(size_t)r1 * FOP + jb]     = v10;
            if (ok1 && jb + 1 < FO) g_hB[(size_t)r1 * FOP + jb + 1] = v11;
            if (STATS) {
                float s0 = (ok0 ? v00 : 0.f) + (ok1 ? v10 : 0.f);
                float q0 = (ok0 ? v00 * v00 : 0.f) + (ok1 ? v10 * v10 : 0.f);
                float s1 = (ok0 ? v01 : 0.f) + (ok1 ? v11 : 0.f);
                float q1 = (ok0 ? v01 * v01 : 0.f) + (ok1 ? v11 * v11 : 0.f);
                lsum[ni * 2 + 0] += s0; lsq[ni * 2 + 0] += q0;
                lsum[ni * 2 + 1] += s1; lsq[ni * 2 + 1] += q1;
            }
        }
    }
    if (STATS) {
        __syncthreads();
        #pragma unroll
        for (int ni = 0; ni < 4; ni++) {
            int col0 = nwarp + ni * 8 + 2 * tg;
            atomicAdd(&sred[col0], lsum[ni * 2 + 0]);
            atomicAdd(&sqred[col0], lsq[ni * 2 + 0]);
            atomicAdd(&sred[col0 + 1], lsum[ni * 2 + 1]);
            atomicAdd(&sqred[col0 + 1], lsq[ni * 2 + 1]);
        }
        __syncthreads();
        if (tid < 64) {
            int j = j0 + tid;
            if (j < FO) {
                atomicAdd(&g_stats[j], sred[tid]);
                atomicAdd(&g_stats[256 + j], sqred[tid]);
            }
        }
    }
}

// ---------------- fused mean-pool + MLP head (hB stride 200) ----------------
__global__ void __launch_bounds__(256) k_poolmlp(const float* __restrict__ Wl1,
                                                 const float* __restrict__ bl1,
                                                 const float* __restrict__ Wl2,
                                                 const float* __restrict__ bl2,
                                                 float* __restrict__ out) {
    const int FO = 199, FOP = 200;
    __shared__ float pooled[FO];
    __shared__ float t1[49];
    int g = blockIdx.x;
    int s = g_gstart[g], e = g_gstart[g + 1];
    int f = threadIdx.x;
    if (f < FO) {
        float acc = 0.f;
        for (int n = s; n < e; n++) acc += g_hB[(size_t)n * FOP + f];
        int cnt = e - s;
        pooled[f] = acc / (float)(cnt > 0 ? cnt : 1);
    }
    __syncthreads();
    if (f < 49) {
        float a = bl1[f];
        for (int k = 0; k < FO; k++) a += pooled[k] * Wl1[k * 49 + f];
        t1[f] = a;
    }
    __syncthreads();
    if (f < 2) {
        float a = bl2[f];
        for (int k = 0; k < 49; k++) a += t1[k] * Wl2[k * 2 + f];
        out[g * 2 + f] = a;
    }
}

// ---------------- launch ----------------
extern "C" void kernel_launch(void* const* d_in, const int* in_sizes, int n_in,
                              void* d_out, int out_size) {
    const float* x     = (const float*)d_in[0];
    const void*  ei    = d_in[1];
    const void*  batch = d_in[2];
    const float* bn0g = (const float*)d_in[3];
    const float* bn0b = (const float*)d_in[4];
    const float* bn1g = (const float*)d_in[5];
    const float* bn1b = (const float*)d_in[6];
    const float* bn2g = (const float*)d_in[7];
    const float* bn2b = (const float*)d_in[8];
    const float* W1  = (const float*)d_in[9];
    const float* b1  = (const float*)d_in[10];
    const float* W2  = (const float*)d_in[11];
    const float* b2  = (const float*)d_in[12];
    const float* W3  = (const float*)d_in[13];
    const float* b3  = (const float*)d_in[14];
    const float* Wl1 = (const float*)d_in[15];
    const float* bl1 = (const float*)d_in[16];
    const float* Wl2 = (const float*)d_in[17];
    const float* bl2 = (const float*)d_in[18];
    float* out = (float*)d_out;

    const int NB_N = (N_NODES + 255) / 256;
    const int NB_E = (N_EDGES + 255) / 256;

    // graph preprocessing
    k_init<<<NB_N, 256>>>((const int*)ei);
    k_deg_edges<<<NB_E, 256>>>(ei);
    k_scan1<<<SCAN_BLOCKS, 256>>>();
    k_scan2<<<1, 256>>>(batch);
    k_scan3<<<NB_N, 256>>>();
    k_fill<<<NB_E, 256>>>(ei);

    dim3 sblk(32, 8);
    const int NB_G8  = ((N_NODES * 8)  + 255) / 256;
    const int NB_G18 = ((N_NODES * 18) + 255) / 256;
    const int NB_G34 = ((N_NODES * 34) + 255) / 256;
    const int GX = N_PAD / 128;

    // ---- layer 1
    k_stats_x<<<dim3(1, 64), sblk>>>(x, 7);
    k_finalize<<<1, 256>>>(bn0g, bn0b, 7);
    k_gather1<<<NB_G8, 256>>>(x);
    k_gemm_mma<7, 8, 71, 72, true><<<dim3(GX, 2), 256>>>(W1, b1);

    // ---- layer 2
    k_finalize<<<1, 256>>>(bn1g, bn1b, 71);
    k_gatherv<18><<<NB_G18, 256>>>();
    k_gemm_mma<71, 72, 135, 136, true><<<dim3(GX, 3), 256>>>(W2, b2);

    // ---- layer 3
    k_finalize<<<1, 256>>>(bn2g, bn2b, 135);
    k_gatherv<34><<<NB_G34, 256>>>();
    k_gemm_mma<135, 136, 199, 200, false><<<dim3(GX, 4), 256>>>(W3, b3);

    // ---- pool + head
    k_poolmlp<<<N_GRAPHS, 256>>>(Wl1, bl1, Wl2, bl2, out);
}

// round 10
// speedup vs baseline: 1.5702x; 1.2814x over previous
#include <cuda_runtime.h>
#include <cuda_fp16.h>
#include <math.h>
#include <stdint.h>

#define N_NODES 100000
#define N_PAD   100096   // multiple of 128
#define N_EDGES 1600000
#define N_TOT   1700000
#define N_GRAPHS 256
#define BN_EPS 1e-5f

#define SCAN_BLOCKS 512
#define SCAN_CHUNK  ((N_NODES + SCAN_BLOCKS - 1) / SCAN_BLOCKS)   // 196

// ---------------- scratch (device globals; no runtime allocation) -------------
__device__ int    g_idx64;
__device__ int    g_deg[N_NODES];
__device__ float  g_dinv[N_NODES];
__device__ int    g_off[N_NODES + 1];
__device__ int    g_blocksum[SCAN_BLOCKS];
__device__ int    g_cursor[N_NODES];
__device__ int    g_srcarr[N_TOT];
__device__ float  g_normarr[N_TOT];
__device__ __half g_hA[(size_t)N_PAD * 200];   // aggregated (BN'd) input, fp16
__device__ __half g_hB[(size_t)N_PAD * 200];   // layer output, fp16
__device__ float  g_stats[512];
__device__ float  g_scale[256];
__device__ float  g_shift[256];
__device__ int    g_gstart[N_GRAPHS + 1];

__device__ __forceinline__ int idx_at(const void* p, long i, int is64) {
    if (is64) return (int)((const long long*)p)[i];
    return ((const int*)p)[i];
}

// ---------------- init ----------------
__global__ void __launch_bounds__(256) k_init(const int* __restrict__ ei32) {
    int n = blockIdx.x * blockDim.x + threadIdx.x;
    if (n < N_NODES) g_deg[n] = 1;
    if (n < 512) g_stats[n] = 0.0f;
    if (n == 0) {
        int any = 0;
        for (int k = 0; k < 64; k++)
            if (ei32[2 * k + 1] != 0) { any = 1; break; }
        g_idx64 = !any;
    }
}

__global__ void __launch_bounds__(256) k_deg_edges(const void* __restrict__ ei) {
    int e = blockIdx.x * blockDim.x + threadIdx.x;
    if (e < N_EDGES) {
        int is64 = g_idx64;
        int d = idx_at(ei, (long)N_EDGES + e, is64);
        if ((unsigned)d < N_NODES) atomicAdd(&g_deg[d], 1);
    }
}

__global__ void __launch_bounds__(256) k_scan1() {
    __shared__ int sh[256];
    int b = blockIdx.x, t = threadIdx.x;
    int idx = b * SCAN_CHUNK + t;
    int v = 0;
    if (t < SCAN_CHUNK && idx < N_NODES) {
        v = g_deg[idx];
        g_dinv[idx] = rsqrtf((float)v);
    }
    sh[t] = v;
    __syncthreads();
    for (int o = 1; o < 256; o <<= 1) {
        int a = (t >= o) ? sh[t - o] : 0;
        __syncthreads();
        sh[t] += a;
        __syncthreads();
    }
    if (t < SCAN_CHUNK && idx < N_NODES) g_off[idx] = sh[t] - v;
    if (t == 255) g_blocksum[b] = sh[255];
}

__global__ void __launch_bounds__(256) k_scan2(const void* __restrict__ batch) {
    __shared__ int sh[256];
    int t = threadIdx.x;
    int a0 = g_blocksum[2 * t];
    int a1 = g_blocksum[2 * t + 1];
    sh[t] = a0 + a1;
    __syncthreads();
    for (int o = 1; o < 256; o <<= 1) {
        int v = (t >= o) ? sh[t - o] : 0;
        __syncthreads();
        sh[t] += v;
        __syncthreads();
    }
    int pre = (t == 0) ? 0 : sh[t - 1];
    g_blocksum[2 * t] = pre;
    g_blocksum[2 * t + 1] = pre + a0;
    if (t == 255) g_off[N_NODES] = sh[255];
    int is64 = g_idx64;
    int lo = 0, hi = N_NODES;
    while (lo < hi) {
        int mid = (lo + hi) >> 1;
        if (idx_at(batch, mid, is64) < t) lo = mid + 1; else hi = mid;
    }
    g_gstart[t] = lo;
    if (t == 0) g_gstart[N_GRAPHS] = N_NODES;
}

__global__ void __launch_bounds__(256) k_scan3() {
    int n = blockIdx.x * blockDim.x + threadIdx.x;
    if (n < N_NODES) {
        int o = g_off[n] + g_blocksum[n / SCAN_CHUNK];
        g_off[n] = o;
        g_srcarr[o] = n;
        float di = g_dinv[n];
        g_normarr[o] = di * di;
        g_cursor[n] = o + 1;
    }
}

__global__ void __launch_bounds__(256) k_fill(const void* __restrict__ ei) {
    int e = blockIdx.x * blockDim.x + threadIdx.x;
    if (e < N_EDGES) {
        int is64 = g_idx64;
        int s = idx_at(ei, e, is64);
        int d = idx_at(ei, (long)N_EDGES + e, is64);
        if ((unsigned)s < N_NODES && (unsigned)d < N_NODES) {
            int pos = atomicAdd(&g_cursor[d], 1);
            if ((unsigned)pos < N_TOT) {
                g_srcarr[pos] = s;
                g_normarr[pos] = g_dinv[s] * g_dinv[d];
            }
        }
    }
}

// ---------------- stats over external x (layer 0 only) ----------------
__global__ void __launch_bounds__(256) k_stats_x(const float* __restrict__ x, int FI) {
    int f = threadIdx.x;
    float s = 0.f, sq = 0.f;
    if (f < FI) {
        for (int n = blockIdx.y * blockDim.y + threadIdx.y; n < N_NODES;
             n += gridDim.y * blockDim.y) {
            float v = x[(size_t)n * FI + f];
            s += v;
            sq += v * v;
        }
    }
    __shared__ float shs[8][32];
    __shared__ float shq[8][32];
    shs[threadIdx.y][threadIdx.x] = s;
    shq[threadIdx.y][threadIdx.x] = sq;
    __syncthreads();
    if (threadIdx.y == 0 && f < FI) {
        float ts = 0.f, tq = 0.f;
        #pragma unroll
        for (int y = 0; y < 8; y++) { ts += shs[y][threadIdx.x]; tq += shq[y][threadIdx.x]; }
        atomicAdd(&g_stats[f], ts);
        atomicAdd(&g_stats[256 + f], tq);
    }
}

__global__ void __launch_bounds__(256) k_finalize(const float* __restrict__ gam,
                                                  const float* __restrict__ bet, int FI) {
    int k = threadIdx.x;
    if (k < FI) {
        float m = g_stats[k] * (1.0f / N_NODES);
        float v = g_stats[256 + k] * (1.0f / N_NODES) - m * m;
        float a = gam[k] * rsqrtf(v + BN_EPS);
        g_scale[k] = a;
        g_shift[k] = bet[k] - m * a;
    } else {
        g_scale[k] = 0.f;
        g_shift[k] = 0.f;
    }
    g_stats[k] = 0.f;
    g_stats[256 + k] = 0.f;
}

// ---------------- layer-1 gather (external fp32 x, FI=7 -> padded 8) ---------
__global__ void __launch_bounds__(256) k_gather1(const float* __restrict__ x) {
    const int FI = 7, FIP = 8, LPN = 8;
    int gid = blockIdx.x * blockDim.x + threadIdx.x;
    int node = gid / LPN;
    int lane = gid % LPN;
    if (node >= N_NODES) return;
    int beg = g_off[node], end = g_off[node + 1];
    float acc = 0.f, sumw = 0.f;
    for (int e = beg; e < end; e++) {
        int s = __ldg(&g_srcarr[e]);
        float wn = __ldg(&g_normarr[e]);
        sumw += wn;
        if (lane < FI) acc += wn * __ldg(&x[(size_t)s * FI + lane]);
    }
    float r = g_scale[lane] * acc + g_shift[lane] * sumw;
    g_hA[(size_t)node * FIP + lane] = __float2half_rn(r);
}

// ---------------- fp16 gather: LPN lanes/node, 8 halves (uint4) per lane -----
template <int LPN>
__global__ void __launch_bounds__(256) k_gatherh() {
    int gid = blockIdx.x * blockDim.x + threadIdx.x;
    int node = gid / LPN;
    int lane = gid - node * LPN;
    if (node >= N_NODES) return;
    int beg = g_off[node], end = g_off[node + 1];
    const uint4* in8 = (const uint4*)g_hB;
    uint4* out8 = (uint4*)g_hA;
    float acc[8];
    #pragma unroll
    for (int q = 0; q < 8; q++) acc[q] = 0.f;
    float sumw = 0.f;
    for (int e = beg; e < end; e++) {
        int s = __ldg(&g_srcarr[e]);
        float wn = __ldg(&g_normarr[e]);
        sumw += wn;
        uint4 v = __ldg(&in8[(size_t)s * LPN + lane]);
        float2 f0 = __half22float2(*(__half2*)&v.x);
        float2 f1 = __half22float2(*(__half2*)&v.y);
        float2 f2 = __half22float2(*(__half2*)&v.z);
        float2 f3 = __half22float2(*(__half2*)&v.w);
        acc[0] += wn * f0.x; acc[1] += wn * f0.y;
        acc[2] += wn * f1.x; acc[3] += wn * f1.y;
        acc[4] += wn * f2.x; acc[5] += wn * f2.y;
        acc[6] += wn * f3.x; acc[7] += wn * f3.y;
    }
    int c = lane * 8;
    __half2 h[4];
    #pragma unroll
    for (int q = 0; q < 4; q++) {
        float v0 = g_scale[c + 2 * q]     * acc[2 * q]     + g_shift[c + 2 * q]     * sumw;
        float v1 = g_scale[c + 2 * q + 1] * acc[2 * q + 1] + g_shift[c + 2 * q + 1] * sumw;
        h[q] = __floats2half2_rn(v0, v1);
    }
    uint4 o;
    o.x = *(uint32_t*)&h[0]; o.y = *(uint32_t*)&h[1];
    o.z = *(uint32_t*)&h[2]; o.w = *(uint32_t*)&h[3];
    out8[(size_t)node * LPN + lane] = o;
}

// ---------------- fp16 mma GEMM v3: hB = relu(hA @ W + bias) -----------------
// CTA = 64 rows x full FO (NJ chunks of 64 looped inside; A staged once).
// 8 warps: 2 M x 4 N; warp tile 32x16; mma m16n8k16 f16->f32.
template <int FI, int FIP, int KPAD, int FO, int FOP, int NJ, bool STATS>
__global__ void __launch_bounds__(256) k_gemm_h(const float* __restrict__ W,
                                                const float* __restrict__ bias) {
    const int SA = KPAD + 8;            // half units; conflict-free strides
    __shared__ __half Asm[64 * SA];
    __shared__ __half Wsm[64 * SA];
    __shared__ float  sred[64];
    __shared__ float  sqred[64];

    int tid = threadIdx.x;
    int wid = tid >> 5, lane = tid & 31;
    int grp = lane >> 2, tg = lane & 3;
    int mwarp = (wid & 1) * 32;
    int nwarp = (wid >> 1) * 16;
    int n0 = blockIdx.x * 64;

    // stage A once: 64 rows x KPAD halves (zero pad k >= FIP, rows >= N_NODES)
    {
        const int VR = KPAD / 8;  // uint4 per row
        const uint4* src = (const uint4*)g_hA;
        for (int idx = tid; idx < 64 * VR; idx += 256) {
            int r = idx / VR, q = idx - r * VR;
            uint4 v = make_uint4(0, 0, 0, 0);
            if (n0 + r < N_NODES && q < FIP / 8)
                v = __ldg(&src[(size_t)(n0 + r) * (FIP / 8) + q]);
            *(uint4*)&Asm[r * SA + q * 8] = v;
        }
    }

    for (int jc = 0; jc < NJ; jc++) {
        int j0 = jc * 64;
        __syncthreads();   // protect Wsm/sred from previous iteration readers
        // stage W chunk transposed: Wsm[n][k] = W[k][j0+n]
        for (int idx = tid; idx < 64 * KPAD; idx += 256) {
            int nn = idx / KPAD, k = idx - nn * KPAD;
            float v = (k < FI && (j0 + nn) < FO) ? __ldg(&W[k * FO + j0 + nn]) : 0.f;
            Wsm[nn * SA + k] = __float2half_rn(v);
        }
        if (STATS && tid < 64) { sred[tid] = 0.f; sqred[tid] = 0.f; }
        __syncthreads();

        float c[2][2][4];
        #pragma unroll
        for (int mi = 0; mi < 2; mi++)
            #pragma unroll
            for (int ni = 0; ni < 2; ni++)
                #pragma unroll
                for (int q = 0; q < 4; q++) c[mi][ni][q] = 0.f;

        const int NS = KPAD / 16;
        #pragma unroll
        for (int ks = 0; ks < NS; ks++) {
            int kb = ks * 16;
            uint32_t a[2][4];
            #pragma unroll
            for (int mi = 0; mi < 2; mi++) {
                int row = mwarp + mi * 16 + grp;
                const __half* ap = &Asm[row * SA + kb + 2 * tg];
                a[mi][0] = *(const uint32_t*)ap;
                a[mi][1] = *(const uint32_t*)(ap + 8 * SA);
                a[mi][2] = *(const uint32_t*)(ap + 8);
                a[mi][3] = *(const uint32_t*)(ap + 8 * SA + 8);
            }
            uint32_t b[2][2];
            #pragma unroll
            for (int ni = 0; ni < 2; ni++) {
                int nn = nwarp + ni * 8 + grp;
                const __half* bp = &Wsm[nn * SA + kb + 2 * tg];
                b[ni][0] = *(const uint32_t*)bp;
                b[ni][1] = *(const uint32_t*)(bp + 8);
            }
            #pragma unroll
            for (int mi = 0; mi < 2; mi++)
                #pragma unroll
                for (int ni = 0; ni < 2; ni++) {
                    asm volatile(
                        "mma.sync.aligned.m16n8k16.row.col.f32.f16.f16.f32 "
                        "{%0,%1,%2,%3}, {%4,%5,%6,%7}, {%8,%9}, {%0,%1,%2,%3};"
                        : "+f"(c[mi][ni][0]), "+f"(c[mi][ni][1]),
                          "+f"(c[mi][ni][2]), "+f"(c[mi][ni][3])
                        : "r"(a[mi][0]), "r"(a[mi][1]), "r"(a[mi][2]), "r"(a[mi][3]),
                          "r"(b[ni][0]), "r"(b[ni][1]));
                }
        }

        // epilogue: bias + relu, fp16 store, stats
        #pragma unroll
        for (int mi = 0; mi < 2; mi++) {
            int r0 = n0 + mwarp + mi * 16 + grp;
            int r1 = r0 + 8;
            #pragma unroll
            for (int ni = 0; ni < 2; ni++) {
                int jb = j0 + nwarp + ni * 8 + 2 * tg;   // even; jb+1 <= FO <= FOP-1
                if (jb >= FO) continue;
                float bj0 = __ldg(&bias[jb]);
                float bj1 = (jb + 1 < FO) ? __ldg(&bias[jb + 1]) : 0.f;
                float v00 = c[mi][ni][0] + bj0; v00 = v00 > 0.f ? v00 : 0.f;
                float v01 = c[mi][ni][1] + bj1; v01 = v01 > 0.f ? v01 : 0.f;
                float v10 = c[mi][ni][2] + bj0; v10 = v10 > 0.f ? v10 : 0.f;
                float v11 = c[mi][ni][3] + bj1; v11 = v11 > 0.f ? v11 : 0.f;
                if (jb + 1 >= FO) { v01 = 0.f; v11 = 0.f; }
                bool ok0 = (r0 < N_NODES), ok1 = (r1 < N_NODES);
                __half2 p0 = __floats2half2_rn(v00, v01);
                __half2 p1 = __floats2half2_rn(v10, v11);
                if (ok0) *(uint32_t*)&g_hB[(size_t)r0 * FOP + jb] = *(uint32_t*)&p0;
                if (ok1) *(uint32_t*)&g_hB[(size_t)r1 * FOP + jb] = *(uint32_t*)&p1;
                if (STATS) {
                    float s0 = (ok0 ? v00 : 0.f) + (ok1 ? v10 : 0.f);
                    float q0 = (ok0 ? v00 * v00 : 0.f) + (ok1 ? v10 * v10 : 0.f);
                    float s1 = (ok0 ? v01 : 0.f) + (ok1 ? v11 : 0.f);
                    float q1 = (ok0 ? v01 * v01 : 0.f) + (ok1 ? v11 * v11 : 0.f);
                    int cb = nwarp + ni * 8 + 2 * tg;
                    atomicAdd(&sred[cb], s0);
                    atomicAdd(&sqred[cb], q0);
                    atomicAdd(&sred[cb + 1], s1);
                    atomicAdd(&sqred[cb + 1], q1);
                }
            }
        }
        if (STATS) {
            __syncthreads();
            if (tid < 64) {
                int j = j0 + tid;
                if (j < FO) {
                    atomicAdd(&g_stats[j], sred[tid]);
                    atomicAdd(&g_stats[256 + j], sqred[tid]);
                }
            }
        }
    }
}

// ---------------- fused mean-pool + MLP head (hB fp16, stride 200) ----------
__global__ void __launch_bounds__(256) k_poolmlp(const float* __restrict__ Wl1,
                                                 const float* __restrict__ bl1,
                                                 const float* __restrict__ Wl2,
                                                 const float* __restrict__ bl2,
                                                 float* __restrict__ out) {
    const int FO = 199, FOP = 200;
    __shared__ float pooled[FO];
    __shared__ float t1[49];
    int g = blockIdx.x;
    int s = g_gstart[g], e = g_gstart[g + 1];
    int f = threadIdx.x;
    if (f < FO) {
        float acc = 0.f;
        for (int n = s; n < e; n++) acc += __half2float(g_hB[(size_t)n * FOP + f]);
        int cnt = e - s;
        pooled[f] = acc / (float)(cnt > 0 ? cnt : 1);
    }
    __syncthreads();
    if (f < 49) {
        float a = bl1[f];
        for (int k = 0; k < FO; k++) a += pooled[k] * Wl1[k * 49 + f];
        t1[f] = a;
    }
    __syncthreads();
    if (f < 2) {
        float a = bl2[f];
        for (int k = 0; k < 49; k++) a += t1[k] * Wl2[k * 2 + f];
        out[g * 2 + f] = a;
    }
}

// ---------------- launch ----------------
extern "C" void kernel_launch(void* const* d_in, const int* in_sizes, int n_in,
                              void* d_out, int out_size) {
    const float* x     = (const float*)d_in[0];
    const void*  ei    = d_in[1];
    const void*  batch = d_in[2];
    const float* bn0g = (const float*)d_in[3];
    const float* bn0b = (const float*)d_in[4];
    const float* bn1g = (const float*)d_in[5];
    const float* bn1b = (const float*)d_in[6];
    const float* bn2g = (const float*)d_in[7];
    const float* bn2b = (const float*)d_in[8];
    const float* W1  = (const float*)d_in[9];
    const float* b1  = (const float*)d_in[10];
    const float* W2  = (const float*)d_in[11];
    const float* b2  = (const float*)d_in[12];
    const float* W3  = (const float*)d_in[13];
    const float* b3  = (const float*)d_in[14];
    const float* Wl1 = (const float*)d_in[15];
    const float* bl1 = (const float*)d_in[16];
    const float* Wl2 = (const float*)d_in[17];
    const float* bl2 = (const float*)d_in[18];
    float* out = (float*)d_out;

    const int NB_N = (N_NODES + 255) / 256;
    const int NB_E = (N_EDGES + 255) / 256;

    // graph preprocessing
    k_init<<<NB_N, 256>>>((const int*)ei);
    k_deg_edges<<<NB_E, 256>>>(ei);
    k_scan1<<<SCAN_BLOCKS, 256>>>();
    k_scan2<<<1, 256>>>(batch);
    k_scan3<<<NB_N, 256>>>();
    k_fill<<<NB_E, 256>>>(ei);

    dim3 sblk(32, 8);
    const int NB_G8  = ((N_NODES * 8)  + 255) / 256;
    const int NB_G9  = ((N_NODES * 9)  + 255) / 256;
    const int NB_G17 = ((N_NODES * 17) + 255) / 256;
    const int GX64 = N_PAD / 64;

    // ---- layer 1: FI=7 (FIP=8, KPAD=16), FO=71 (FOP=72, NJ=2)
    k_stats_x<<<dim3(1, 64), sblk>>>(x, 7);
    k_finalize<<<1, 256>>>(bn0g, bn0b, 7);
    k_gather1<<<NB_G8, 256>>>(x);
    k_gemm_h<7, 8, 16, 71, 72, 2, true><<<GX64, 256>>>(W1, b1);

    // ---- layer 2: FI=71 (FIP=72, KPAD=80), FO=135 (FOP=136, NJ=3)
    k_finalize<<<1, 256>>>(bn1g, bn1b, 71);
    k_gatherh<9><<<NB_G9, 256>>>();
    k_gemm_h<71, 72, 80, 135, 136, 3, true><<<GX64, 256>>>(W2, b2);

    // ---- layer 3: FI=135 (FIP=136, KPAD=144), FO=199 (FOP=200, NJ=4)
    k_finalize<<<1, 256>>>(bn2g, bn2b, 135);
    k_gatherh<17><<<NB_G17, 256>>>();
    k_gemm_h<135, 136, 144, 199, 200, 4, false><<<GX64, 256>>>(W3, b3);

    // ---- pool + head
    k_poolmlp<<<N_GRAPHS, 256>>>(Wl1, bl1, Wl2, bl2, out);
}